// round 12
// baseline (speedup 1.0000x reference)
#include <cuda_runtime.h>
#include <cuda_fp16.h>
#include <math.h>

#define Nn 8192
#define Dd 512
#define SEGCAP 128   // per-1024-segment candidate cap (exact fallback if hit)

// ---------------- static device scratch (symbol-access only) ----------------
static __device__ float  d_K  [(size_t)Nn * Nn];   // log_K fp32 (exact grid)
static __device__ float  d_KT [(size_t)Nn * Nn];   // transpose (same bits)
static __device__ __half d_Kh [(size_t)Nn * Nn];   // fp16 screening copy
static __device__ __half d_KTh[(size_t)Nn * Nn];   // fp16 screening copy (T)
static __device__ float d_alpha[Nn];
static __device__ float d_beta [Nn];
static __device__ float d_pA [Nn], d_pB [Nn];      // state 1 iter back
static __device__ float d_p2A[Nn], d_p2B[Nn];      // state 2 iters back
static __device__ float d_xsq[Nn];
static __device__ float d_ysq[Nn];
static __device__ int   d_idx[Nn];
static __device__ int   g_done;

// ---- FROZEN NUMERICS (Round 8 pass): XLA-CPU cephes exp, FMA-contracted ----
static __device__ __forceinline__ float exp_fma(float x) {
    x = fminf(x, 88.3762626647950f);
    x = fmaxf(x, -88.3762626647949f);
    float fx = floorf(__fmaf_rn(x, 1.44269504088896341f, 0.5f));
    float r  = __fmaf_rn(fx, -0.693359375f, x);
    r        = __fmaf_rn(fx,  2.12194440e-4f, r);
    float z  = __fmul_rn(r, r);
    float y  = __fmaf_rn(1.9875691500e-4f, r, 1.3981999507e-3f);
    y = __fmaf_rn(y, r, 8.3334519073e-3f);
    y = __fmaf_rn(y, r, 4.1665795894e-2f);
    y = __fmaf_rn(y, r, 1.6666665459e-1f);
    y = __fmaf_rn(y, r, 5.0000001201e-1f);
    y = __fmaf_rn(y, z, r);
    y = __fadd_rn(1.0f, y);
    int n = (int)fx;
    float s = __int_as_float((unsigned)(n + 127) << 23);
    return __fmul_rn(y, s);
}

// ---- FROZEN: XLA-CPU cephes log, FMA-contracted (S >= 1 here) ----
static __device__ __forceinline__ float log_fma(float x) {
    int bits = __float_as_int(x);
    int e = (bits >> 23) - 126;
    float mant = __int_as_float((bits & 0x007fffff) | 0x3f000000);  // [0.5,1)
    if (mant < 0.707106781186547524f) {
        e -= 1;
        mant = __fadd_rn(__fadd_rn(mant, mant), -1.0f);
    } else {
        mant = __fadd_rn(mant, -1.0f);
    }
    float z = __fmul_rn(mant, mant);
    float y = 7.0376836292e-2f;
    y = __fmaf_rn(y, mant, -1.1514610310e-1f);
    y = __fmaf_rn(y, mant,  1.1676998740e-1f);
    y = __fmaf_rn(y, mant, -1.2420140846e-1f);
    y = __fmaf_rn(y, mant,  1.4249322787e-1f);
    y = __fmaf_rn(y, mant, -1.6668057665e-1f);
    y = __fmaf_rn(y, mant,  2.0000714765e-1f);
    y = __fmaf_rn(y, mant, -2.4999993993e-1f);
    y = __fmaf_rn(y, mant,  3.3333331174e-1f);
    y = __fmul_rn(__fmul_rn(y, mant), z);
    float fe = (float)e;
    y = __fmaf_rn(fe, -2.12194440e-4f, y);
    y = __fmaf_rn(-0.5f, z, y);
    float res = __fadd_rn(mant, y);
    res = __fmaf_rn(fe, 0.693359375f, res);
    return res;
}

// ---------------- init ----------------
__global__ void init_kernel() {
    int i = blockIdx.x * blockDim.x + threadIdx.x;
    if (i < Nn) {
        d_beta[i] = 0.0f; d_alpha[i] = 0.0f;
        d_pA [i] = __int_as_float(0x7fc00000);   // sentinel (cur is never NaN)
        d_pB [i] = __int_as_float(0x7fc00000);
        d_p2A[i] = __int_as_float(0x7fc00000);
        d_p2B[i] = __int_as_float(0x7fc00000);
    }
    if (i == 0) g_done = 0;
}

// ---------------- row squared norms: 8-slot FMA chains (FROZEN) -------------
__global__ void rowsq_kernel(const float* __restrict__ X0,
                             const float* __restrict__ X1) {
    int half = (gridDim.x * blockDim.x) >> 1;
    int g = blockIdx.x * blockDim.x + threadIdx.x;
    bool second = g >= half;
    int row = second ? (g - half) : g;
    const float* x = (second ? X1 : X0) + (size_t)row * Dd;
    float s[8];
#pragma unroll
    for (int i = 0; i < 8; i++) s[i] = 0.0f;
    for (int k = 0; k < Dd; k += 8) {
#pragma unroll
        for (int i = 0; i < 8; i++) {
            float v = x[k + i];
            s[i] = __fmaf_rn(v, v, s[i]);
        }
    }
    float w0 = __fadd_rn(s[0], s[4]);
    float w1 = __fadd_rn(s[1], s[5]);
    float w2 = __fadd_rn(s[2], s[6]);
    float w3 = __fadd_rn(s[3], s[7]);
    float r = __fadd_rn(__fadd_rn(w0, w2), __fadd_rn(w1, w3));
    if (second) d_ysq[row] = r; else d_xsq[row] = r;
}

// ---------------- GEMM -> K fp32 + fp16 copy (FROZEN fp32 numerics) ---------
__global__ void __launch_bounds__(256) gemm_kernel(const float* __restrict__ A,
                                                   const float* __restrict__ B) {
    __shared__ float As[8][128];
    __shared__ float Bs[8][128];
    int bi = blockIdx.y << 7, bj = blockIdx.x << 7;
    int t  = threadIdx.x;
    int tx = t & 15, ty = t >> 4;
    int lrow = t & 127;
    int lk   = (t >> 7) << 2;

    float acc[8][8];
#pragma unroll
    for (int i = 0; i < 8; i++)
#pragma unroll
        for (int j = 0; j < 8; j++) acc[i][j] = 0.f;

    const float* Ag = A + (size_t)(bi + lrow) * Dd + lk;
    const float* Bg = B + (size_t)(bj + lrow) * Dd + lk;

    for (int kt = 0; kt < Dd; kt += 8) {
        float4 av = *(const float4*)(Ag + kt);
        float4 bv = *(const float4*)(Bg + kt);
        __syncthreads();
        As[lk + 0][lrow] = av.x; As[lk + 1][lrow] = av.y;
        As[lk + 2][lrow] = av.z; As[lk + 3][lrow] = av.w;
        Bs[lk + 0][lrow] = bv.x; Bs[lk + 1][lrow] = bv.y;
        Bs[lk + 2][lrow] = bv.z; Bs[lk + 3][lrow] = bv.w;
        __syncthreads();
#pragma unroll
        for (int k = 0; k < 8; k++) {
            float a[8], b[8];
            *(float4*)&a[0] = *(const float4*)&As[k][(ty << 3)];
            *(float4*)&a[4] = *(const float4*)&As[k][(ty << 3) + 4];
            *(float4*)&b[0] = *(const float4*)&Bs[k][(tx << 3)];
            *(float4*)&b[4] = *(const float4*)&Bs[k][(tx << 3) + 4];
#pragma unroll
            for (int i = 0; i < 8; i++)
#pragma unroll
                for (int j = 0; j < 8; j++)
                    acc[i][j] = __fmaf_rn(a[i], b[j], acc[i][j]);
        }
    }

    int row0 = bi + (ty << 3);
    int col0 = bj + (tx << 3);
    float xs[8], ys[8];
#pragma unroll
    for (int i = 0; i < 8; i++) xs[i] = d_xsq[row0 + i];
#pragma unroll
    for (int j = 0; j < 8; j++) ys[j] = d_ysq[col0 + j];
#pragma unroll
    for (int i = 0; i < 8; i++) {
        float o[8];
        __half hh[8];
#pragma unroll
        for (int j = 0; j < 8; j++) {
            float nrm  = __fadd_rn(xs[i], ys[j]);
            float cost = __fmaf_rn(-2.0f, acc[i][j], nrm);
            o[j] = __fdiv_rn(-cost, 0.1f);
            hh[j] = __float2half(o[j]);
        }
        *(float4*)&d_K[(size_t)(row0 + i) * Nn + col0]     = *(float4*)&o[0];
        *(float4*)&d_K[(size_t)(row0 + i) * Nn + col0 + 4] = *(float4*)&o[4];
        *(uint4*)&d_Kh[(size_t)(row0 + i) * Nn + col0]     = *(uint4*)hh;
    }
}

// ---------------- transpose: K -> KT (fp32) + KTh (fp16), one-time ----------
__global__ void transpose_kernel() {
    __shared__ float tile[32][33];
    int tx = threadIdx.x, ty = threadIdx.y;
    int xi = (blockIdx.x << 5) + tx;
    int yi = (blockIdx.y << 5) + ty;
#pragma unroll
    for (int j = 0; j < 32; j += 8)
        tile[ty + j][tx] = d_K[(size_t)(yi + j) * Nn + xi];
    __syncthreads();
    int xo = (blockIdx.y << 5) + tx;
    int yo = (blockIdx.x << 5) + ty;
#pragma unroll
    for (int j = 0; j < 32; j += 8) {
        float v = tile[tx][ty + j];
        d_KT [(size_t)(yo + j) * Nn + xo] = v;
        d_KTh[(size_t)(yo + j) * Nn + xo] = __float2half(v);
    }
}

// ====== LSE PASS: fp16 screen (half DRAM) + exact fp32 candidate gather =====
// |K| < 16384 => fp16 error <= 8; screen at z_h >= m_h - 96 provably supersets
// the true candidate set {z >= m-70} and contains the argmax. Exact z for the
// superset is gathered from fp32 K; exact max recomputed; filter + FROZEN-order
// sum => bit-identical to the full-precision pass.
template <int DIR>
__global__ void __launch_bounds__(256) lse_pass_kernel() {
    if (g_done) return;
    __shared__ float z[Nn];            // approx z (screening), 32 KB
    __shared__ float wmax[8];
    __shared__ float bmax_s;
    __shared__ int   seg_cnt[8];
    __shared__ short seg_list[8][SEGCAP];
    __shared__ float seg_zex[8][SEGCAP];

    int row = blockIdx.x;
    int t   = threadIdx.x;
    int lane = t & 31, wid = t >> 5;
    const __half* __restrict__ Hs = ((DIR == 0) ? d_Kh : d_KTh) + (size_t)row * Nn;
    const float*  __restrict__ Mx = ((DIR == 0) ? d_K  : d_KT ) + (size_t)row * Nn;
    const float*  __restrict__ vin = (DIR == 0) ? d_beta : d_alpha;

    // screening load: 16 KB of fp16 + beta, stage approx z, track approx max
    float lm = __int_as_float(0xff800000);
#pragma unroll
    for (int c = 0; c < 4; c++) {
        int base = c * 2048 + t * 8;
        uint4 hv = ((const uint4*)Hs)[c * 256 + t];
        __half2* hp = (__half2*)&hv;
        float4 b0 = *(const float4*)(vin + base);
        float4 b1 = *(const float4*)(vin + base + 4);
        float2 f0 = __half22float2(hp[0]);
        float2 f1 = __half22float2(hp[1]);
        float2 f2 = __half22float2(hp[2]);
        float2 f3 = __half22float2(hp[3]);
        float4 z0, z1;
        z0.x = __fadd_rn(f0.x, b0.x); z0.y = __fadd_rn(f0.y, b0.y);
        z0.z = __fadd_rn(f1.x, b0.z); z0.w = __fadd_rn(f1.y, b0.w);
        z1.x = __fadd_rn(f2.x, b1.x); z1.y = __fadd_rn(f2.y, b1.y);
        z1.z = __fadd_rn(f3.x, b1.z); z1.w = __fadd_rn(f3.y, b1.w);
        *(float4*)&z[base]     = z0;
        *(float4*)&z[base + 4] = z1;
        lm = fmaxf(lm, fmaxf(fmaxf(z0.x, z0.y), fmaxf(z0.z, z0.w)));
        lm = fmaxf(lm, fmaxf(fmaxf(z1.x, z1.y), fmaxf(z1.z, z1.w)));
    }
#pragma unroll
    for (int off = 16; off; off >>= 1)
        lm = fmaxf(lm, __shfl_down_sync(0xffffffffu, lm, off));
    if (lane == 0) { wmax[wid] = lm; seg_cnt[wid] = 0; }
    __syncthreads();

    if (wid == 0) {
        float m = (lane < 8) ? wmax[lane] : __int_as_float(0xff800000);
#pragma unroll
        for (int off = 4; off; off >>= 1)
            m = fmaxf(m, __shfl_down_sync(0xffffffffu, m, off));
        if (lane == 0) bmax_s = m;
    }
    __syncthreads();
    float thr_s = bmax_s - 96.0f;   // superset threshold (fp16 margin proof)

    // segmented ballot scan (ascending within each warp segment)
    {
        int base = wid * 1024;
        int cnt = 0;
#pragma unroll 4
        for (int k = 0; k < 32; k++) {
            float v = z[base + k * 32 + lane];   // conflict-free
            unsigned mask = __ballot_sync(0xffffffffu, v >= thr_s);
            if (lane == 0) {
                while (mask) {
                    int b = __ffs(mask) - 1;
                    if (cnt < SEGCAP) seg_list[wid][cnt] = (short)(k * 32 + b);
                    cnt++;
                    mask &= mask - 1;
                }
            }
        }
        if (lane == 0) seg_cnt[wid] = cnt;
        __syncwarp();
        // warp-parallel gather of EXACT z for this segment's candidates
        int cc = seg_cnt[wid]; if (cc > SEGCAP) cc = SEGCAP;
        for (int p = lane; p < cc; p += 32) {
            int idx = base + seg_list[wid][p];
            seg_zex[wid][p] = __fadd_rn(Mx[idx], vin[idx]);
        }
    }
    __syncthreads();

    if (t == 0) {
        bool ok = true;
#pragma unroll
        for (int w = 0; w < 8; w++) ok &= (seg_cnt[w] <= SEGCAP);

        float S, m;
        if (ok) {
            // exact max over superset (contains true argmax)
            m = __int_as_float(0xff800000);
            for (int w = 0; w < 8; w++) {
                int cnt = seg_cnt[w];
                for (int p = 0; p < cnt; p++) m = fmaxf(m, seg_zex[w][p]);
            }
            float thr = m - 70.0f;
            if (DIR == 0) {
                float s[8];
#pragma unroll
                for (int i = 0; i < 8; i++) s[i] = 0.0f;
                for (int w = 0; w < 8; w++) {
                    int base = w * 1024, cnt = seg_cnt[w];
                    for (int p = 0; p < cnt; p++) {
                        float zv = seg_zex[w][p];
                        if (zv >= thr) {
                            int idx = base + seg_list[w][p];
                            s[idx & 7] = __fadd_rn(s[idx & 7], exp_fma(__fadd_rn(zv, -m)));
                        }
                    }
                }
                float w0 = __fadd_rn(s[0], s[4]);
                float w1 = __fadd_rn(s[1], s[5]);
                float w2 = __fadd_rn(s[2], s[6]);
                float w3 = __fadd_rn(s[3], s[7]);
                S = __fadd_rn(__fadd_rn(w0, w2), __fadd_rn(w1, w3));
            } else {
                float acc = 0.0f;
                for (int w = 0; w < 8; w++) {
                    int cnt = seg_cnt[w];
                    for (int p = 0; p < cnt; p++) {
                        float zv = seg_zex[w][p];
                        if (zv >= thr)
                            acc = __fadd_rn(acc, exp_fma(__fadd_rn(zv, -m)));
                    }
                }
                S = acc;
            }
        } else {
            // exact in-order fallback: full fp32 row from global (never expected)
            m = __int_as_float(0xff800000);
            for (int q = 0; q < Nn; q++)
                m = fmaxf(m, __fadd_rn(Mx[q], vin[q]));
            float thr = m - 70.0f;
            if (DIR == 0) {
                float s[8];
#pragma unroll
                for (int i = 0; i < 8; i++) s[i] = 0.0f;
                for (int q = 0; q < Nn; q++) {
                    float zv = __fadd_rn(Mx[q], vin[q]);
                    if (zv >= thr)
                        s[q & 7] = __fadd_rn(s[q & 7], exp_fma(__fadd_rn(zv, -m)));
                }
                float w0 = __fadd_rn(s[0], s[4]);
                float w1 = __fadd_rn(s[1], s[5]);
                float w2 = __fadd_rn(s[2], s[6]);
                float w3 = __fadd_rn(s[3], s[7]);
                S = __fadd_rn(__fadd_rn(w0, w2), __fadd_rn(w1, w3));
            } else {
                float acc = 0.0f;
                for (int q = 0; q < Nn; q++) {
                    float zv = __fadd_rn(Mx[q], vin[q]);
                    if (zv >= thr)
                        acc = __fadd_rn(acc, exp_fma(__fadd_rn(zv, -m)));
                }
                S = acc;
            }
        }
        float res = -__fadd_rn(log_fma(S), m);
        if (DIR == 0) d_alpha[row] = res; else d_beta[row] = res;
    }
}

// ---------- convergence: exact bitwise period-1 / period-2 detection --------
// state_99 = cur  iff  (cur==prev)  or  (cur==prev2 and (99-it) even).
__global__ void __launch_bounds__(1024) conv_kernel(int it) {
    if (g_done) return;
    __shared__ int same1, same2;
    if (threadIdx.x == 0) { same1 = 1; same2 = 1; }
    __syncthreads();
    int l1 = 1, l2 = 1;
    for (int i = threadIdx.x; i < Nn; i += 1024) {
        int ca = __float_as_int(d_alpha[i]), cb = __float_as_int(d_beta[i]);
        int pa = __float_as_int(d_pA [i]),  pb = __float_as_int(d_pB [i]);
        int qa = __float_as_int(d_p2A[i]),  qb = __float_as_int(d_p2B[i]);
        l1 &= (ca == pa) & (cb == pb);
        l2 &= (ca == qa) & (cb == qb);
        d_p2A[i] = d_pA[i]; d_p2B[i] = d_pB[i];
        d_pA [i] = d_alpha[i]; d_pB [i] = d_beta[i];
    }
    if (!l1) atomicAnd(&same1, 0);
    if (!l2) atomicAnd(&same2, 0);
    __syncthreads();
    if (threadIdx.x == 0) {
        if (same1 || (same2 && (((99 - it) & 1) == 0))) g_done = 1;
    }
}

// ---------------- argmax over P = exp_fma(fl(fl(K+alpha)+beta)) (FROZEN) ----
__global__ void __launch_bounds__(256) argmax_kernel() {
    int rowbase = blockIdx.x << 3;
    int t = threadIdx.x;
    float a[8];
#pragma unroll
    for (int r = 0; r < 8; r++) a[r] = d_alpha[rowbase + r];

    float bv[8]; int bi_[8];
#pragma unroll
    for (int r = 0; r < 8; r++) { bv[r] = -1.0f; bi_[r] = Nn; }

    for (int c = t << 2; c < Nn; c += 1024) {
        float4 betav = *(const float4*)(d_beta + c);
#pragma unroll
        for (int r = 0; r < 8; r++) {
            float4 v = *(const float4*)(d_K + (size_t)(rowbase + r) * Nn + c);
            float w;
            w = exp_fma(__fadd_rn(__fadd_rn(v.x, a[r]), betav.x)); if (w > bv[r]) { bv[r] = w; bi_[r] = c; }
            w = exp_fma(__fadd_rn(__fadd_rn(v.y, a[r]), betav.y)); if (w > bv[r]) { bv[r] = w; bi_[r] = c + 1; }
            w = exp_fma(__fadd_rn(__fadd_rn(v.z, a[r]), betav.z)); if (w > bv[r]) { bv[r] = w; bi_[r] = c + 2; }
            w = exp_fma(__fadd_rn(__fadd_rn(v.w, a[r]), betav.w)); if (w > bv[r]) { bv[r] = w; bi_[r] = c + 3; }
        }
    }
#pragma unroll
    for (int r = 0; r < 8; r++) {
#pragma unroll
        for (int off = 16; off; off >>= 1) {
            float ov = __shfl_down_sync(0xffffffffu, bv[r], off);
            int   oi = __shfl_down_sync(0xffffffffu, bi_[r], off);
            if (ov > bv[r] || (ov == bv[r] && oi < bi_[r])) { bv[r] = ov; bi_[r] = oi; }
        }
    }
    __shared__ float svv[8][8];
    __shared__ int   sii[8][8];
    int wid = t >> 5, lane = t & 31;
    if (lane == 0) {
#pragma unroll
        for (int r = 0; r < 8; r++) { svv[r][wid] = bv[r]; sii[r][wid] = bi_[r]; }
    }
    __syncthreads();
    if (t < 8) {
        float V = -1.0f; int I = Nn;
#pragma unroll
        for (int w = 0; w < 8; w++) {
            float ov = svv[t][w]; int oi = sii[t][w];
            if (ov > V || (ov == V && oi < I)) { V = ov; I = oi; }
        }
        d_idx[rowbase + t] = I;
    }
}

// ---------------- out = concat(x0, x1[idx]) ----------------
__global__ void output_kernel(const float* __restrict__ x0,
                              const float* __restrict__ x1,
                              float* __restrict__ out) {
    int row = blockIdx.x;
    int t   = threadIdx.x;
    const float4* s0 = (const float4*)(x0 + (size_t)row * Dd);
    ((float4*)(out + (size_t)row * Dd))[t] = s0[t];
    int j = d_idx[row];
    const float4* s1 = (const float4*)(x1 + (size_t)j * Dd);
    ((float4*)(out + (size_t)Nn * Dd + (size_t)row * Dd))[t] = s1[t];
}

// ---------------- launch ----------------
extern "C" void kernel_launch(void* const* d_in, const int* in_sizes, int n_in,
                              void* d_out, int out_size) {
    const float* x0 = (const float*)d_in[0];
    const float* x1 = (const float*)d_in[1];
    float* out = (float*)d_out;

    init_kernel<<<8, 1024>>>();
    rowsq_kernel<<<2 * (Nn / 256), 256>>>(x0, x1);

    dim3 gg(Nn / 128, Nn / 128);
    gemm_kernel<<<gg, 256>>>(x0, x1);

    dim3 tg(Nn / 32, Nn / 32), tb(32, 8);
    transpose_kernel<<<tg, tb>>>();

    for (int it = 0; it < 100; it++) {
        lse_pass_kernel<0><<<Nn, 256>>>();
        lse_pass_kernel<1><<<Nn, 256>>>();
        conv_kernel<<<1, 1024>>>(it);
    }

    argmax_kernel<<<Nn / 8, 256>>>();
    output_kernel<<<Nn, 128>>>(x0, x1, out);
}

// round 13
// speedup vs baseline: 1.2429x; 1.2429x over previous
#include <cuda_runtime.h>
#include <cuda_fp16.h>
#include <math.h>

#define Nn 8192
#define Dd 512
#define SEGCAP 192   // per-1024-segment candidate cap (exact fallback if hit)

// ---------------- static device scratch (symbol-access only) ----------------
static __device__ float  d_K  [(size_t)Nn * Nn];   // log_K fp32 (exact grid)
static __device__ float  d_KT [(size_t)Nn * Nn];   // transpose (same bits)
static __device__ __half d_Kh [(size_t)Nn * Nn];   // fp16 screening copy
static __device__ __half d_KTh[(size_t)Nn * Nn];   // fp16 screening copy (T)
static __device__ float d_alpha[Nn];
static __device__ float d_beta [Nn];
static __device__ float d_pA [Nn], d_pB [Nn];      // state 2 iters back
static __device__ float d_xsq[Nn];
static __device__ float d_ysq[Nn];
static __device__ int   d_idx[Nn];
static __device__ int   g_done;

// ---- FROZEN NUMERICS (Round 8 pass): XLA-CPU cephes exp, FMA-contracted ----
static __device__ __forceinline__ float exp_fma(float x) {
    x = fminf(x, 88.3762626647950f);
    x = fmaxf(x, -88.3762626647949f);
    float fx = floorf(__fmaf_rn(x, 1.44269504088896341f, 0.5f));
    float r  = __fmaf_rn(fx, -0.693359375f, x);
    r        = __fmaf_rn(fx,  2.12194440e-4f, r);
    float z  = __fmul_rn(r, r);
    float y  = __fmaf_rn(1.9875691500e-4f, r, 1.3981999507e-3f);
    y = __fmaf_rn(y, r, 8.3334519073e-3f);
    y = __fmaf_rn(y, r, 4.1665795894e-2f);
    y = __fmaf_rn(y, r, 1.6666665459e-1f);
    y = __fmaf_rn(y, r, 5.0000001201e-1f);
    y = __fmaf_rn(y, z, r);
    y = __fadd_rn(1.0f, y);
    int n = (int)fx;
    float s = __int_as_float((unsigned)(n + 127) << 23);
    return __fmul_rn(y, s);
}

// ---- FROZEN: XLA-CPU cephes log, FMA-contracted (S >= 1 here) ----
static __device__ __forceinline__ float log_fma(float x) {
    int bits = __float_as_int(x);
    int e = (bits >> 23) - 126;
    float mant = __int_as_float((bits & 0x007fffff) | 0x3f000000);  // [0.5,1)
    if (mant < 0.707106781186547524f) {
        e -= 1;
        mant = __fadd_rn(__fadd_rn(mant, mant), -1.0f);
    } else {
        mant = __fadd_rn(mant, -1.0f);
    }
    float z = __fmul_rn(mant, mant);
    float y = 7.0376836292e-2f;
    y = __fmaf_rn(y, mant, -1.1514610310e-1f);
    y = __fmaf_rn(y, mant,  1.1676998740e-1f);
    y = __fmaf_rn(y, mant, -1.2420140846e-1f);
    y = __fmaf_rn(y, mant,  1.4249322787e-1f);
    y = __fmaf_rn(y, mant, -1.6668057665e-1f);
    y = __fmaf_rn(y, mant,  2.0000714765e-1f);
    y = __fmaf_rn(y, mant, -2.4999993993e-1f);
    y = __fmaf_rn(y, mant,  3.3333331174e-1f);
    y = __fmul_rn(__fmul_rn(y, mant), z);
    float fe = (float)e;
    y = __fmaf_rn(fe, -2.12194440e-4f, y);
    y = __fmaf_rn(-0.5f, z, y);
    float res = __fadd_rn(mant, y);
    res = __fmaf_rn(fe, 0.693359375f, res);
    return res;
}

// ---------------- init ----------------
__global__ void init_kernel() {
    int i = blockIdx.x * blockDim.x + threadIdx.x;
    if (i < Nn) {
        d_beta[i] = 0.0f; d_alpha[i] = 0.0f;
        d_pA[i] = __int_as_float(0x7fc00000);   // sentinel (cur never NaN)
        d_pB[i] = __int_as_float(0x7fc00000);
    }
    if (i == 0) g_done = 0;
}

// ---------------- row squared norms: 8-slot FMA chains (FROZEN) -------------
__global__ void rowsq_kernel(const float* __restrict__ X0,
                             const float* __restrict__ X1) {
    int half = (gridDim.x * blockDim.x) >> 1;
    int g = blockIdx.x * blockDim.x + threadIdx.x;
    bool second = g >= half;
    int row = second ? (g - half) : g;
    const float* x = (second ? X1 : X0) + (size_t)row * Dd;
    float s[8];
#pragma unroll
    for (int i = 0; i < 8; i++) s[i] = 0.0f;
    for (int k = 0; k < Dd; k += 8) {
#pragma unroll
        for (int i = 0; i < 8; i++) {
            float v = x[k + i];
            s[i] = __fmaf_rn(v, v, s[i]);
        }
    }
    float w0 = __fadd_rn(s[0], s[4]);
    float w1 = __fadd_rn(s[1], s[5]);
    float w2 = __fadd_rn(s[2], s[6]);
    float w3 = __fadd_rn(s[3], s[7]);
    float r = __fadd_rn(__fadd_rn(w0, w2), __fadd_rn(w1, w3));
    if (second) d_ysq[row] = r; else d_xsq[row] = r;
}

// ---------------- GEMM -> K fp32 + fp16 copy (FROZEN fp32 numerics) ---------
__global__ void __launch_bounds__(256) gemm_kernel(const float* __restrict__ A,
                                                   const float* __restrict__ B) {
    __shared__ float As[8][128];
    __shared__ float Bs[8][128];
    int bi = blockIdx.y << 7, bj = blockIdx.x << 7;
    int t  = threadIdx.x;
    int tx = t & 15, ty = t >> 4;
    int lrow = t & 127;
    int lk   = (t >> 7) << 2;

    float acc[8][8];
#pragma unroll
    for (int i = 0; i < 8; i++)
#pragma unroll
        for (int j = 0; j < 8; j++) acc[i][j] = 0.f;

    const float* Ag = A + (size_t)(bi + lrow) * Dd + lk;
    const float* Bg = B + (size_t)(bj + lrow) * Dd + lk;

    for (int kt = 0; kt < Dd; kt += 8) {
        float4 av = *(const float4*)(Ag + kt);
        float4 bv = *(const float4*)(Bg + kt);
        __syncthreads();
        As[lk + 0][lrow] = av.x; As[lk + 1][lrow] = av.y;
        As[lk + 2][lrow] = av.z; As[lk + 3][lrow] = av.w;
        Bs[lk + 0][lrow] = bv.x; Bs[lk + 1][lrow] = bv.y;
        Bs[lk + 2][lrow] = bv.z; Bs[lk + 3][lrow] = bv.w;
        __syncthreads();
#pragma unroll
        for (int k = 0; k < 8; k++) {
            float a[8], b[8];
            *(float4*)&a[0] = *(const float4*)&As[k][(ty << 3)];
            *(float4*)&a[4] = *(const float4*)&As[k][(ty << 3) + 4];
            *(float4*)&b[0] = *(const float4*)&Bs[k][(tx << 3)];
            *(float4*)&b[4] = *(const float4*)&Bs[k][(tx << 3) + 4];
#pragma unroll
            for (int i = 0; i < 8; i++)
#pragma unroll
                for (int j = 0; j < 8; j++)
                    acc[i][j] = __fmaf_rn(a[i], b[j], acc[i][j]);
        }
    }

    int row0 = bi + (ty << 3);
    int col0 = bj + (tx << 3);
    float xs[8], ys[8];
#pragma unroll
    for (int i = 0; i < 8; i++) xs[i] = d_xsq[row0 + i];
#pragma unroll
    for (int j = 0; j < 8; j++) ys[j] = d_ysq[col0 + j];
#pragma unroll
    for (int i = 0; i < 8; i++) {
        float o[8];
        __half hh[8];
#pragma unroll
        for (int j = 0; j < 8; j++) {
            float nrm  = __fadd_rn(xs[i], ys[j]);
            float cost = __fmaf_rn(-2.0f, acc[i][j], nrm);
            o[j] = __fdiv_rn(-cost, 0.1f);
            hh[j] = __float2half(o[j]);
        }
        *(float4*)&d_K[(size_t)(row0 + i) * Nn + col0]     = *(float4*)&o[0];
        *(float4*)&d_K[(size_t)(row0 + i) * Nn + col0 + 4] = *(float4*)&o[4];
        *(uint4*)&d_Kh[(size_t)(row0 + i) * Nn + col0]     = *(uint4*)hh;
    }
}

// ---------------- transpose: K -> KT (fp32) + KTh (fp16), one-time ----------
__global__ void transpose_kernel() {
    __shared__ float tile[32][33];
    int tx = threadIdx.x, ty = threadIdx.y;
    int xi = (blockIdx.x << 5) + tx;
    int yi = (blockIdx.y << 5) + ty;
#pragma unroll
    for (int j = 0; j < 32; j += 8)
        tile[ty + j][tx] = d_K[(size_t)(yi + j) * Nn + xi];
    __syncthreads();
    int xo = (blockIdx.y << 5) + tx;
    int yo = (blockIdx.x << 5) + ty;
#pragma unroll
    for (int j = 0; j < 32; j += 8) {
        float v = tile[tx][ty + j];
        d_KT [(size_t)(yo + j) * Nn + xo] = v;
        d_KTh[(size_t)(yo + j) * Nn + xo] = __float2half(v);
    }
}

// ====== LSE PASS: fp16 screen, half2 smem stage, parallel exp ===============
// Screening z staged as half2 (16 KB). |z_scr - z_exact| <= 16, |m_s - m| <= 8
// => threshold m_s - 112 supersets {z >= m-70} and contains the argmax.
// Exact fp32 z gathered for superset (warp-parallel), exact max recomputed,
// exps computed warp-parallel, thread 0 does only the FROZEN-order additions:
//   DIR=0 (alpha): 8-slot (j mod 8) + halving combine; DIR=1: sequential.
template <int DIR>
__global__ void __launch_bounds__(256) lse_pass_kernel() {
    if (g_done) return;
    __shared__ __half2 zh[Nn / 2];     // 16 KB screening stage
    __shared__ float wmax[8];
    __shared__ float bmax_s, m_sh;
    __shared__ int   ok_s;
    __shared__ int   seg_cnt[8];
    __shared__ short seg_list[8][SEGCAP];
    __shared__ float seg_val[8][SEGCAP];

    int row = blockIdx.x;
    int t   = threadIdx.x;
    int lane = t & 31, wid = t >> 5;
    const __half* __restrict__ Hs = ((DIR == 0) ? d_Kh : d_KTh) + (size_t)row * Nn;
    const float*  __restrict__ Mx = ((DIR == 0) ? d_K  : d_KT ) + (size_t)row * Nn;
    const float*  __restrict__ vin = (DIR == 0) ? d_beta : d_alpha;

    // screening load: fp16 K + fp32 v -> approx z -> half2 smem; track max
    float lm = __int_as_float(0xff800000);
#pragma unroll
    for (int c = 0; c < 4; c++) {
        int base = c * 2048 + t * 8;
        uint4 hv = ((const uint4*)Hs)[c * 256 + t];
        __half2* hp = (__half2*)&hv;
        float4 b0 = *(const float4*)(vin + base);
        float4 b1 = *(const float4*)(vin + base + 4);
        float2 f0 = __half22float2(hp[0]);
        float2 f1 = __half22float2(hp[1]);
        float2 f2 = __half22float2(hp[2]);
        float2 f3 = __half22float2(hp[3]);
        float z0 = __fadd_rn(f0.x, b0.x), z1 = __fadd_rn(f0.y, b0.y);
        float z2 = __fadd_rn(f1.x, b0.z), z3 = __fadd_rn(f1.y, b0.w);
        float z4 = __fadd_rn(f2.x, b1.x), z5 = __fadd_rn(f2.y, b1.y);
        float z6 = __fadd_rn(f3.x, b1.z), z7 = __fadd_rn(f3.y, b1.w);
        int hb = base >> 1;
        zh[hb + 0] = __floats2half2_rn(z0, z1);
        zh[hb + 1] = __floats2half2_rn(z2, z3);
        zh[hb + 2] = __floats2half2_rn(z4, z5);
        zh[hb + 3] = __floats2half2_rn(z6, z7);
        lm = fmaxf(lm, fmaxf(fmaxf(z0, z1), fmaxf(z2, z3)));
        lm = fmaxf(lm, fmaxf(fmaxf(z4, z5), fmaxf(z6, z7)));
    }
#pragma unroll
    for (int off = 16; off; off >>= 1)
        lm = fmaxf(lm, __shfl_down_sync(0xffffffffu, lm, off));
    if (lane == 0) { wmax[wid] = lm; seg_cnt[wid] = 0; }
    __syncthreads();

    if (wid == 0) {
        float m = (lane < 8) ? wmax[lane] : __int_as_float(0xff800000);
#pragma unroll
        for (int off = 4; off; off >>= 1)
            m = fmaxf(m, __shfl_down_sync(0xffffffffu, m, off));
        if (lane == 0) bmax_s = m;
    }
    __syncthreads();
    float thr_s = bmax_s - 112.0f;  // superset threshold (fp16 margin proof)

    // segmented ballot scan over half2 stage (ascending within segment)
    {
        int hbase = wid * 512;       // 1024 floats = 512 half2 per segment
        int cnt = 0;
        for (int g = 0; g < 16; g++) {
            float2 f = __half22float2(zh[hbase + g * 32 + lane]);  // conflict-free
            unsigned m0 = __ballot_sync(0xffffffffu, f.x >= thr_s);
            unsigned m1 = __ballot_sync(0xffffffffu, f.y >= thr_s);
            if (lane == 0) {
                while (m0 | m1) {
                    int b0 = m0 ? (__ffs(m0) - 1) : 99;
                    int b1 = m1 ? (__ffs(m1) - 1) : 99;
                    int loc;
                    if (b0 <= b1) { loc = 2 * b0;     m0 &= m0 - 1; }
                    else          { loc = 2 * b1 + 1; m1 &= m1 - 1; }
                    if (cnt < SEGCAP) seg_list[wid][cnt] = (short)(g * 64 + loc);
                    cnt++;
                }
            }
        }
        if (lane == 0) seg_cnt[wid] = cnt;
        __syncwarp();
        int cc = seg_cnt[wid]; if (cc > SEGCAP) cc = SEGCAP;
        // warp-parallel gather of EXACT z for this segment's candidates
        for (int p = lane; p < cc; p += 32) {
            int idx = wid * 1024 + seg_list[wid][p];
            seg_val[wid][p] = __fadd_rn(Mx[idx], vin[idx]);
        }
    }
    __syncthreads();

    // thread 0: exact max over superset; set ok flag
    if (t == 0) {
        bool ok = true;
#pragma unroll
        for (int w = 0; w < 8; w++) ok &= (seg_cnt[w] <= SEGCAP);
        ok_s = ok;
        if (ok) {
            float m = __int_as_float(0xff800000);
            for (int w = 0; w < 8; w++) {
                int cnt = seg_cnt[w];
                for (int p = 0; p < cnt; p++) m = fmaxf(m, seg_val[w][p]);
            }
            m_sh = m;
        }
    }
    __syncthreads();

    if (ok_s) {
        // warp-parallel exps (order-independent); -1 marks filtered-out
        float m = m_sh;
        float thr = m - 70.0f;
        int cc = seg_cnt[wid];
        for (int p = lane; p < cc; p += 32) {
            float zv = seg_val[wid][p];
            seg_val[wid][p] = (zv >= thr) ? exp_fma(__fadd_rn(zv, -m)) : -1.0f;
        }
        __syncthreads();

        if (t == 0) {
            float S;
            if (DIR == 0) {
                float s[8];
#pragma unroll
                for (int i = 0; i < 8; i++) s[i] = 0.0f;
                for (int w = 0; w < 8; w++) {
                    int base = w * 1024, cnt = seg_cnt[w];
                    for (int p = 0; p < cnt; p++) {
                        float e = seg_val[w][p];
                        if (e >= 0.0f) {
                            int idx = base + seg_list[w][p];
                            s[idx & 7] = __fadd_rn(s[idx & 7], e);
                        }
                    }
                }
                float w0 = __fadd_rn(s[0], s[4]);
                float w1 = __fadd_rn(s[1], s[5]);
                float w2 = __fadd_rn(s[2], s[6]);
                float w3 = __fadd_rn(s[3], s[7]);
                S = __fadd_rn(__fadd_rn(w0, w2), __fadd_rn(w1, w3));
            } else {
                float acc = 0.0f;
                for (int w = 0; w < 8; w++) {
                    int cnt = seg_cnt[w];
                    for (int p = 0; p < cnt; p++) {
                        float e = seg_val[w][p];
                        if (e >= 0.0f) acc = __fadd_rn(acc, e);
                    }
                }
                S = acc;
            }
            float res = -__fadd_rn(log_fma(S), m);
            if (DIR == 0) d_alpha[row] = res; else d_beta[row] = res;
        }
    } else if (t == 0) {
        // exact in-order fallback over full fp32 row (never expected)
        float m = __int_as_float(0xff800000);
        for (int q = 0; q < Nn; q++)
            m = fmaxf(m, __fadd_rn(Mx[q], vin[q]));
        float thr = m - 70.0f;
        float S;
        if (DIR == 0) {
            float s[8];
#pragma unroll
            for (int i = 0; i < 8; i++) s[i] = 0.0f;
            for (int q = 0; q < Nn; q++) {
                float zv = __fadd_rn(Mx[q], vin[q]);
                if (zv >= thr)
                    s[q & 7] = __fadd_rn(s[q & 7], exp_fma(__fadd_rn(zv, -m)));
            }
            float w0 = __fadd_rn(s[0], s[4]);
            float w1 = __fadd_rn(s[1], s[5]);
            float w2 = __fadd_rn(s[2], s[6]);
            float w3 = __fadd_rn(s[3], s[7]);
            S = __fadd_rn(__fadd_rn(w0, w2), __fadd_rn(w1, w3));
        } else {
            float acc = 0.0f;
            for (int q = 0; q < Nn; q++) {
                float zv = __fadd_rn(Mx[q], vin[q]);
                if (zv >= thr)
                    acc = __fadd_rn(acc, exp_fma(__fadd_rn(zv, -m)));
            }
            S = acc;
        }
        float res = -__fadd_rn(log_fma(S), m);
        if (DIR == 0) d_alpha[row] = res; else d_beta[row] = res;
    }
}

// -------- convergence: bitwise vs state 2 iters back (period 1 & 2) ---------
// Called at odd it => (99-it) even => period-2 parity is always correct.
__global__ void __launch_bounds__(1024) conv_kernel() {
    if (g_done) return;
    __shared__ int diff;
    if (threadIdx.x == 0) diff = 0;
    __syncthreads();
    int ld = 0;
    for (int i = threadIdx.x; i < Nn; i += 1024) {
        ld |= (__float_as_int(d_alpha[i]) != __float_as_int(d_pA[i]));
        ld |= (__float_as_int(d_beta[i])  != __float_as_int(d_pB[i]));
        d_pA[i] = d_alpha[i];
        d_pB[i] = d_beta[i];
    }
    if (ld) atomicOr(&diff, 1);
    __syncthreads();
    if (threadIdx.x == 0 && diff == 0) g_done = 1;
}

// ---------------- argmax over P = exp_fma(fl(fl(K+alpha)+beta)) (FROZEN) ----
__global__ void __launch_bounds__(256) argmax_kernel() {
    int rowbase = blockIdx.x << 3;
    int t = threadIdx.x;
    float a[8];
#pragma unroll
    for (int r = 0; r < 8; r++) a[r] = d_alpha[rowbase + r];

    float bv[8]; int bi_[8];
#pragma unroll
    for (int r = 0; r < 8; r++) { bv[r] = -1.0f; bi_[r] = Nn; }

    for (int c = t << 2; c < Nn; c += 1024) {
        float4 betav = *(const float4*)(d_beta + c);
#pragma unroll
        for (int r = 0; r < 8; r++) {
            float4 v = *(const float4*)(d_K + (size_t)(rowbase + r) * Nn + c);
            float w;
            w = exp_fma(__fadd_rn(__fadd_rn(v.x, a[r]), betav.x)); if (w > bv[r]) { bv[r] = w; bi_[r] = c; }
            w = exp_fma(__fadd_rn(__fadd_rn(v.y, a[r]), betav.y)); if (w > bv[r]) { bv[r] = w; bi_[r] = c + 1; }
            w = exp_fma(__fadd_rn(__fadd_rn(v.z, a[r]), betav.z)); if (w > bv[r]) { bv[r] = w; bi_[r] = c + 2; }
            w = exp_fma(__fadd_rn(__fadd_rn(v.w, a[r]), betav.w)); if (w > bv[r]) { bv[r] = w; bi_[r] = c + 3; }
        }
    }
#pragma unroll
    for (int r = 0; r < 8; r++) {
#pragma unroll
        for (int off = 16; off; off >>= 1) {
            float ov = __shfl_down_sync(0xffffffffu, bv[r], off);
            int   oi = __shfl_down_sync(0xffffffffu, bi_[r], off);
            if (ov > bv[r] || (ov == bv[r] && oi < bi_[r])) { bv[r] = ov; bi_[r] = oi; }
        }
    }
    __shared__ float svv[8][8];
    __shared__ int   sii[8][8];
    int wid = t >> 5, lane = t & 31;
    if (lane == 0) {
#pragma unroll
        for (int r = 0; r < 8; r++) { svv[r][wid] = bv[r]; sii[r][wid] = bi_[r]; }
    }
    __syncthreads();
    if (t < 8) {
        float V = -1.0f; int I = Nn;
#pragma unroll
        for (int w = 0; w < 8; w++) {
            float ov = svv[t][w]; int oi = sii[t][w];
            if (ov > V || (ov == V && oi < I)) { V = ov; I = oi; }
        }
        d_idx[rowbase + t] = I;
    }
}

// ---------------- out = concat(x0, x1[idx]) ----------------
__global__ void output_kernel(const float* __restrict__ x0,
                              const float* __restrict__ x1,
                              float* __restrict__ out) {
    int row = blockIdx.x;
    int t   = threadIdx.x;
    const float4* s0 = (const float4*)(x0 + (size_t)row * Dd);
    ((float4*)(out + (size_t)row * Dd))[t] = s0[t];
    int j = d_idx[row];
    const float4* s1 = (const float4*)(x1 + (size_t)j * Dd);
    ((float4*)(out + (size_t)Nn * Dd + (size_t)row * Dd))[t] = s1[t];
}

// ---------------- launch ----------------
extern "C" void kernel_launch(void* const* d_in, const int* in_sizes, int n_in,
                              void* d_out, int out_size) {
    const float* x0 = (const float*)d_in[0];
    const float* x1 = (const float*)d_in[1];
    float* out = (float*)d_out;

    init_kernel<<<8, 1024>>>();
    rowsq_kernel<<<2 * (Nn / 256), 256>>>(x0, x1);

    dim3 gg(Nn / 128, Nn / 128);
    gemm_kernel<<<gg, 256>>>(x0, x1);

    dim3 tg(Nn / 32, Nn / 32), tb(32, 8);
    transpose_kernel<<<tg, tb>>>();

    for (int it = 0; it < 100; it++) {
        lse_pass_kernel<0><<<Nn, 256>>>();
        lse_pass_kernel<1><<<Nn, 256>>>();
        if (it & 1) conv_kernel<<<1, 1024>>>();
    }

    argmax_kernel<<<Nn / 8, 256>>>();
    output_kernel<<<Nn, 128>>>(x0, x1, out);
}

// round 14
// speedup vs baseline: 1.3026x; 1.0480x over previous
#include <cuda_runtime.h>
#include <cuda_fp16.h>
#include <math.h>

#define Nn 8192
#define Dd 512
#define SEGCAP 192   // per-1024-segment candidate cap (exact fallback if hit)

// ---------------- static device scratch (symbol-access only) ----------------
static __device__ float  d_K  [(size_t)Nn * Nn];   // log_K fp32 (exact grid)
static __device__ float  d_KT [(size_t)Nn * Nn];   // transpose (same bits)
static __device__ __half d_Kh [(size_t)Nn * Nn];   // fp16 screening copy
static __device__ __half d_KTh[(size_t)Nn * Nn];   // fp16 screening copy (T)
static __device__ float d_alpha[Nn];
static __device__ float d_beta [Nn];
static __device__ float d_xsq[Nn];
static __device__ float d_ysq[Nn];
static __device__ int   d_idx[Nn];

// ---- FROZEN NUMERICS (Round 8 pass): XLA-CPU cephes exp, FMA-contracted ----
static __device__ __forceinline__ float exp_fma(float x) {
    x = fminf(x, 88.3762626647950f);
    x = fmaxf(x, -88.3762626647949f);
    float fx = floorf(__fmaf_rn(x, 1.44269504088896341f, 0.5f));
    float r  = __fmaf_rn(fx, -0.693359375f, x);
    r        = __fmaf_rn(fx,  2.12194440e-4f, r);
    float z  = __fmul_rn(r, r);
    float y  = __fmaf_rn(1.9875691500e-4f, r, 1.3981999507e-3f);
    y = __fmaf_rn(y, r, 8.3334519073e-3f);
    y = __fmaf_rn(y, r, 4.1665795894e-2f);
    y = __fmaf_rn(y, r, 1.6666665459e-1f);
    y = __fmaf_rn(y, r, 5.0000001201e-1f);
    y = __fmaf_rn(y, z, r);
    y = __fadd_rn(1.0f, y);
    int n = (int)fx;
    float s = __int_as_float((unsigned)(n + 127) << 23);
    return __fmul_rn(y, s);
}

// ---- FROZEN: XLA-CPU cephes log, FMA-contracted (S >= 1 here) ----
static __device__ __forceinline__ float log_fma(float x) {
    int bits = __float_as_int(x);
    int e = (bits >> 23) - 126;
    float mant = __int_as_float((bits & 0x007fffff) | 0x3f000000);  // [0.5,1)
    if (mant < 0.707106781186547524f) {
        e -= 1;
        mant = __fadd_rn(__fadd_rn(mant, mant), -1.0f);
    } else {
        mant = __fadd_rn(mant, -1.0f);
    }
    float z = __fmul_rn(mant, mant);
    float y = 7.0376836292e-2f;
    y = __fmaf_rn(y, mant, -1.1514610310e-1f);
    y = __fmaf_rn(y, mant,  1.1676998740e-1f);
    y = __fmaf_rn(y, mant, -1.2420140846e-1f);
    y = __fmaf_rn(y, mant,  1.4249322787e-1f);
    y = __fmaf_rn(y, mant, -1.6668057665e-1f);
    y = __fmaf_rn(y, mant,  2.0000714765e-1f);
    y = __fmaf_rn(y, mant, -2.4999993993e-1f);
    y = __fmaf_rn(y, mant,  3.3333331174e-1f);
    y = __fmul_rn(__fmul_rn(y, mant), z);
    float fe = (float)e;
    y = __fmaf_rn(fe, -2.12194440e-4f, y);
    y = __fmaf_rn(-0.5f, z, y);
    float res = __fadd_rn(mant, y);
    res = __fmaf_rn(fe, 0.693359375f, res);
    return res;
}

// ---------------- init ----------------
__global__ void init_kernel() {
    int i = blockIdx.x * blockDim.x + threadIdx.x;
    if (i < Nn) { d_beta[i] = 0.0f; d_alpha[i] = 0.0f; }
}

// ---------------- row squared norms: 8-slot FMA chains (FROZEN) -------------
__global__ void rowsq_kernel(const float* __restrict__ X0,
                             const float* __restrict__ X1) {
    int half = (gridDim.x * blockDim.x) >> 1;
    int g = blockIdx.x * blockDim.x + threadIdx.x;
    bool second = g >= half;
    int row = second ? (g - half) : g;
    const float* x = (second ? X1 : X0) + (size_t)row * Dd;
    float s[8];
#pragma unroll
    for (int i = 0; i < 8; i++) s[i] = 0.0f;
    for (int k = 0; k < Dd; k += 8) {
#pragma unroll
        for (int i = 0; i < 8; i++) {
            float v = x[k + i];
            s[i] = __fmaf_rn(v, v, s[i]);
        }
    }
    float w0 = __fadd_rn(s[0], s[4]);
    float w1 = __fadd_rn(s[1], s[5]);
    float w2 = __fadd_rn(s[2], s[6]);
    float w3 = __fadd_rn(s[3], s[7]);
    float r = __fadd_rn(__fadd_rn(w0, w2), __fadd_rn(w1, w3));
    if (second) d_ysq[row] = r; else d_xsq[row] = r;
}

// ------- GEMM -> K fp32 + fp16 copy. Double-buffered smem, K-tile 16. -------
// FROZEN numerics: each acc[i][j] is ONE ascending-k FMA chain (order
// unchanged by the tiling; only data movement is rescheduled).
__global__ void __launch_bounds__(256) gemm_kernel(const float* __restrict__ A,
                                                   const float* __restrict__ B) {
    __shared__ float As[2][16][128];
    __shared__ float Bs[2][16][128];
    int bi = blockIdx.y << 7, bj = blockIdx.x << 7;
    int t  = threadIdx.x;
    int tx = t & 15, ty = t >> 4;
    int lrow = t & 127;
    int kh   = (t >> 7) << 3;   // 0 or 8

    float acc[8][8];
#pragma unroll
    for (int i = 0; i < 8; i++)
#pragma unroll
        for (int j = 0; j < 8; j++) acc[i][j] = 0.f;

    const float* Ag = A + (size_t)(bi + lrow) * Dd + kh;
    const float* Bg = B + (size_t)(bj + lrow) * Dd + kh;

    float4 pa0 = *(const float4*)(Ag);
    float4 pa1 = *(const float4*)(Ag + 4);
    float4 pb0 = *(const float4*)(Bg);
    float4 pb1 = *(const float4*)(Bg + 4);

    // stage tile 0
    As[0][kh + 0][lrow] = pa0.x; As[0][kh + 1][lrow] = pa0.y;
    As[0][kh + 2][lrow] = pa0.z; As[0][kh + 3][lrow] = pa0.w;
    As[0][kh + 4][lrow] = pa1.x; As[0][kh + 5][lrow] = pa1.y;
    As[0][kh + 6][lrow] = pa1.z; As[0][kh + 7][lrow] = pa1.w;
    Bs[0][kh + 0][lrow] = pb0.x; Bs[0][kh + 1][lrow] = pb0.y;
    Bs[0][kh + 2][lrow] = pb0.z; Bs[0][kh + 3][lrow] = pb0.w;
    Bs[0][kh + 4][lrow] = pb1.x; Bs[0][kh + 5][lrow] = pb1.y;
    Bs[0][kh + 6][lrow] = pb1.z; Bs[0][kh + 7][lrow] = pb1.w;
    __syncthreads();

    int buf = 0;
    for (int kt = 0; kt < Dd; kt += 16) {
        bool last = (kt + 16 >= Dd);
        if (!last) {
            pa0 = *(const float4*)(Ag + kt + 16);
            pa1 = *(const float4*)(Ag + kt + 20);
            pb0 = *(const float4*)(Bg + kt + 16);
            pb1 = *(const float4*)(Bg + kt + 20);
        }
#pragma unroll
        for (int k = 0; k < 16; k++) {          // ascending k — FROZEN chain
            float a[8], b[8];
            *(float4*)&a[0] = *(const float4*)&As[buf][k][(ty << 3)];
            *(float4*)&a[4] = *(const float4*)&As[buf][k][(ty << 3) + 4];
            *(float4*)&b[0] = *(const float4*)&Bs[buf][k][(tx << 3)];
            *(float4*)&b[4] = *(const float4*)&Bs[buf][k][(tx << 3) + 4];
#pragma unroll
            for (int i = 0; i < 8; i++)
#pragma unroll
                for (int j = 0; j < 8; j++)
                    acc[i][j] = __fmaf_rn(a[i], b[j], acc[i][j]);
        }
        if (!last) {
            int nb = buf ^ 1;
            As[nb][kh + 0][lrow] = pa0.x; As[nb][kh + 1][lrow] = pa0.y;
            As[nb][kh + 2][lrow] = pa0.z; As[nb][kh + 3][lrow] = pa0.w;
            As[nb][kh + 4][lrow] = pa1.x; As[nb][kh + 5][lrow] = pa1.y;
            As[nb][kh + 6][lrow] = pa1.z; As[nb][kh + 7][lrow] = pa1.w;
            Bs[nb][kh + 0][lrow] = pb0.x; Bs[nb][kh + 1][lrow] = pb0.y;
            Bs[nb][kh + 2][lrow] = pb0.z; Bs[nb][kh + 3][lrow] = pb0.w;
            Bs[nb][kh + 4][lrow] = pb1.x; Bs[nb][kh + 5][lrow] = pb1.y;
            Bs[nb][kh + 6][lrow] = pb1.z; Bs[nb][kh + 7][lrow] = pb1.w;
        }
        __syncthreads();
        buf ^= 1;
    }

    int row0 = bi + (ty << 3);
    int col0 = bj + (tx << 3);
    float xs[8], ys[8];
#pragma unroll
    for (int i = 0; i < 8; i++) xs[i] = d_xsq[row0 + i];
#pragma unroll
    for (int j = 0; j < 8; j++) ys[j] = d_ysq[col0 + j];
#pragma unroll
    for (int i = 0; i < 8; i++) {
        float o[8];
        __half hh[8];
#pragma unroll
        for (int j = 0; j < 8; j++) {
            float nrm  = __fadd_rn(xs[i], ys[j]);
            float cost = __fmaf_rn(-2.0f, acc[i][j], nrm);
            o[j] = __fdiv_rn(-cost, 0.1f);
            hh[j] = __float2half(o[j]);
        }
        *(float4*)&d_K[(size_t)(row0 + i) * Nn + col0]     = *(float4*)&o[0];
        *(float4*)&d_K[(size_t)(row0 + i) * Nn + col0 + 4] = *(float4*)&o[4];
        *(uint4*)&d_Kh[(size_t)(row0 + i) * Nn + col0]     = *(uint4*)hh;
    }
}

// ---------------- transpose: K -> KT (fp32) + KTh (fp16), one-time ----------
__global__ void transpose_kernel() {
    __shared__ float tile[32][33];
    int tx = threadIdx.x, ty = threadIdx.y;
    int xi = (blockIdx.x << 5) + tx;
    int yi = (blockIdx.y << 5) + ty;
#pragma unroll
    for (int j = 0; j < 32; j += 8)
        tile[ty + j][tx] = d_K[(size_t)(yi + j) * Nn + xi];
    __syncthreads();
    int xo = (blockIdx.y << 5) + tx;
    int yo = (blockIdx.x << 5) + ty;
#pragma unroll
    for (int j = 0; j < 32; j += 8) {
        float v = tile[tx][ty + j];
        d_KT [(size_t)(yo + j) * Nn + xo] = v;
        d_KTh[(size_t)(yo + j) * Nn + xo] = __float2half(v);
    }
}

// ====== LSE PASS: fp16 screen, half2 smem stage, parallel exp (R13) =========
template <int DIR>
__global__ void __launch_bounds__(256) lse_pass_kernel() {
    __shared__ __half2 zh[Nn / 2];     // 16 KB screening stage
    __shared__ float wmax[8];
    __shared__ float bmax_s, m_sh;
    __shared__ int   ok_s;
    __shared__ int   seg_cnt[8];
    __shared__ short seg_list[8][SEGCAP];
    __shared__ float seg_val[8][SEGCAP];

    int row = blockIdx.x;
    int t   = threadIdx.x;
    int lane = t & 31, wid = t >> 5;
    const __half* __restrict__ Hs = ((DIR == 0) ? d_Kh : d_KTh) + (size_t)row * Nn;
    const float*  __restrict__ Mx = ((DIR == 0) ? d_K  : d_KT ) + (size_t)row * Nn;
    const float*  __restrict__ vin = (DIR == 0) ? d_beta : d_alpha;

    float lm = __int_as_float(0xff800000);
#pragma unroll
    for (int c = 0; c < 4; c++) {
        int base = c * 2048 + t * 8;
        uint4 hv = ((const uint4*)Hs)[c * 256 + t];
        __half2* hp = (__half2*)&hv;
        float4 b0 = *(const float4*)(vin + base);
        float4 b1 = *(const float4*)(vin + base + 4);
        float2 f0 = __half22float2(hp[0]);
        float2 f1 = __half22float2(hp[1]);
        float2 f2 = __half22float2(hp[2]);
        float2 f3 = __half22float2(hp[3]);
        float z0 = __fadd_rn(f0.x, b0.x), z1 = __fadd_rn(f0.y, b0.y);
        float z2 = __fadd_rn(f1.x, b0.z), z3 = __fadd_rn(f1.y, b0.w);
        float z4 = __fadd_rn(f2.x, b1.x), z5 = __fadd_rn(f2.y, b1.y);
        float z6 = __fadd_rn(f3.x, b1.z), z7 = __fadd_rn(f3.y, b1.w);
        int hb = base >> 1;
        zh[hb + 0] = __floats2half2_rn(z0, z1);
        zh[hb + 1] = __floats2half2_rn(z2, z3);
        zh[hb + 2] = __floats2half2_rn(z4, z5);
        zh[hb + 3] = __floats2half2_rn(z6, z7);
        lm = fmaxf(lm, fmaxf(fmaxf(z0, z1), fmaxf(z2, z3)));
        lm = fmaxf(lm, fmaxf(fmaxf(z4, z5), fmaxf(z6, z7)));
    }
#pragma unroll
    for (int off = 16; off; off >>= 1)
        lm = fmaxf(lm, __shfl_down_sync(0xffffffffu, lm, off));
    if (lane == 0) { wmax[wid] = lm; seg_cnt[wid] = 0; }
    __syncthreads();

    if (wid == 0) {
        float m = (lane < 8) ? wmax[lane] : __int_as_float(0xff800000);
#pragma unroll
        for (int off = 4; off; off >>= 1)
            m = fmaxf(m, __shfl_down_sync(0xffffffffu, m, off));
        if (lane == 0) bmax_s = m;
    }
    __syncthreads();
    float thr_s = bmax_s - 112.0f;  // superset threshold (fp16 margin proof)

    {
        int hbase = wid * 512;
        int cnt = 0;
        for (int g = 0; g < 16; g++) {
            float2 f = __half22float2(zh[hbase + g * 32 + lane]);  // conflict-free
            unsigned m0 = __ballot_sync(0xffffffffu, f.x >= thr_s);
            unsigned m1 = __ballot_sync(0xffffffffu, f.y >= thr_s);
            if (lane == 0) {
                while (m0 | m1) {
                    int b0 = m0 ? (__ffs(m0) - 1) : 99;
                    int b1 = m1 ? (__ffs(m1) - 1) : 99;
                    int loc;
                    if (b0 <= b1) { loc = 2 * b0;     m0 &= m0 - 1; }
                    else          { loc = 2 * b1 + 1; m1 &= m1 - 1; }
                    if (cnt < SEGCAP) seg_list[wid][cnt] = (short)(g * 64 + loc);
                    cnt++;
                }
            }
        }
        if (lane == 0) seg_cnt[wid] = cnt;
        __syncwarp();
        int cc = seg_cnt[wid]; if (cc > SEGCAP) cc = SEGCAP;
        for (int p = lane; p < cc; p += 32) {
            int idx = wid * 1024 + seg_list[wid][p];
            seg_val[wid][p] = __fadd_rn(Mx[idx], vin[idx]);
        }
    }
    __syncthreads();

    if (t == 0) {
        bool ok = true;
#pragma unroll
        for (int w = 0; w < 8; w++) ok &= (seg_cnt[w] <= SEGCAP);
        ok_s = ok;
        if (ok) {
            float m = __int_as_float(0xff800000);
            for (int w = 0; w < 8; w++) {
                int cnt = seg_cnt[w];
                for (int p = 0; p < cnt; p++) m = fmaxf(m, seg_val[w][p]);
            }
            m_sh = m;
        }
    }
    __syncthreads();

    if (ok_s) {
        float m = m_sh;
        float thr = m - 70.0f;
        int cc = seg_cnt[wid];
        for (int p = lane; p < cc; p += 32) {
            float zv = seg_val[wid][p];
            seg_val[wid][p] = (zv >= thr) ? exp_fma(__fadd_rn(zv, -m)) : -1.0f;
        }
        __syncthreads();

        if (t == 0) {
            float S;
            if (DIR == 0) {
                float s[8];
#pragma unroll
                for (int i = 0; i < 8; i++) s[i] = 0.0f;
                for (int w = 0; w < 8; w++) {
                    int base = w * 1024, cnt = seg_cnt[w];
                    for (int p = 0; p < cnt; p++) {
                        float e = seg_val[w][p];
                        if (e >= 0.0f) {
                            int idx = base + seg_list[w][p];
                            s[idx & 7] = __fadd_rn(s[idx & 7], e);
                        }
                    }
                }
                float w0 = __fadd_rn(s[0], s[4]);
                float w1 = __fadd_rn(s[1], s[5]);
                float w2 = __fadd_rn(s[2], s[6]);
                float w3 = __fadd_rn(s[3], s[7]);
                S = __fadd_rn(__fadd_rn(w0, w2), __fadd_rn(w1, w3));
            } else {
                float acc = 0.0f;
                for (int w = 0; w < 8; w++) {
                    int cnt = seg_cnt[w];
                    for (int p = 0; p < cnt; p++) {
                        float e = seg_val[w][p];
                        if (e >= 0.0f) acc = __fadd_rn(acc, e);
                    }
                }
                S = acc;
            }
            float res = -__fadd_rn(log_fma(S), m);
            if (DIR == 0) d_alpha[row] = res; else d_beta[row] = res;
        }
    } else if (t == 0) {
        // exact in-order fallback over full fp32 row (never expected)
        float m = __int_as_float(0xff800000);
        for (int q = 0; q < Nn; q++)
            m = fmaxf(m, __fadd_rn(Mx[q], vin[q]));
        float thr = m - 70.0f;
        float S;
        if (DIR == 0) {
            float s[8];
#pragma unroll
            for (int i = 0; i < 8; i++) s[i] = 0.0f;
            for (int q = 0; q < Nn; q++) {
                float zv = __fadd_rn(Mx[q], vin[q]);
                if (zv >= thr)
                    s[q & 7] = __fadd_rn(s[q & 7], exp_fma(__fadd_rn(zv, -m)));
            }
            float w0 = __fadd_rn(s[0], s[4]);
            float w1 = __fadd_rn(s[1], s[5]);
            float w2 = __fadd_rn(s[2], s[6]);
            float w3 = __fadd_rn(s[3], s[7]);
            S = __fadd_rn(__fadd_rn(w0, w2), __fadd_rn(w1, w3));
        } else {
            float acc = 0.0f;
            for (int q = 0; q < Nn; q++) {
                float zv = __fadd_rn(Mx[q], vin[q]);
                if (zv >= thr)
                    acc = __fadd_rn(acc, exp_fma(__fadd_rn(zv, -m)));
            }
            S = acc;
        }
        float res = -__fadd_rn(log_fma(S), m);
        if (DIR == 0) d_alpha[row] = res; else d_beta[row] = res;
    }
}

// ---------------- argmax over P = exp_fma(fl(fl(K+alpha)+beta)) (FROZEN) ----
__global__ void __launch_bounds__(256) argmax_kernel() {
    int rowbase = blockIdx.x << 3;
    int t = threadIdx.x;
    float a[8];
#pragma unroll
    for (int r = 0; r < 8; r++) a[r] = d_alpha[rowbase + r];

    float bv[8]; int bi_[8];
#pragma unroll
    for (int r = 0; r < 8; r++) { bv[r] = -1.0f; bi_[r] = Nn; }

    for (int c = t << 2; c < Nn; c += 1024) {
        float4 betav = *(const float4*)(d_beta + c);
#pragma unroll
        for (int r = 0; r < 8; r++) {
            float4 v = *(const float4*)(d_K + (size_t)(rowbase + r) * Nn + c);
            float w;
            w = exp_fma(__fadd_rn(__fadd_rn(v.x, a[r]), betav.x)); if (w > bv[r]) { bv[r] = w; bi_[r] = c; }
            w = exp_fma(__fadd_rn(__fadd_rn(v.y, a[r]), betav.y)); if (w > bv[r]) { bv[r] = w; bi_[r] = c + 1; }
            w = exp_fma(__fadd_rn(__fadd_rn(v.z, a[r]), betav.z)); if (w > bv[r]) { bv[r] = w; bi_[r] = c + 2; }
            w = exp_fma(__fadd_rn(__fadd_rn(v.w, a[r]), betav.w)); if (w > bv[r]) { bv[r] = w; bi_[r] = c + 3; }
        }
    }
#pragma unroll
    for (int r = 0; r < 8; r++) {
#pragma unroll
        for (int off = 16; off; off >>= 1) {
            float ov = __shfl_down_sync(0xffffffffu, bv[r], off);
            int   oi = __shfl_down_sync(0xffffffffu, bi_[r], off);
            if (ov > bv[r] || (ov == bv[r] && oi < bi_[r])) { bv[r] = ov; bi_[r] = oi; }
        }
    }
    __shared__ float svv[8][8];
    __shared__ int   sii[8][8];
    int wid = t >> 5, lane = t & 31;
    if (lane == 0) {
#pragma unroll
        for (int r = 0; r < 8; r++) { svv[r][wid] = bv[r]; sii[r][wid] = bi_[r]; }
    }
    __syncthreads();
    if (t < 8) {
        float V = -1.0f; int I = Nn;
#pragma unroll
        for (int w = 0; w < 8; w++) {
            float ov = svv[t][w]; int oi = sii[t][w];
            if (ov > V || (ov == V && oi < I)) { V = ov; I = oi; }
        }
        d_idx[rowbase + t] = I;
    }
}

// ---------------- out = concat(x0, x1[idx]) ----------------
__global__ void output_kernel(const float* __restrict__ x0,
                              const float* __restrict__ x1,
                              float* __restrict__ out) {
    int row = blockIdx.x;
    int t   = threadIdx.x;
    const float4* s0 = (const float4*)(x0 + (size_t)row * Dd);
    ((float4*)(out + (size_t)row * Dd))[t] = s0[t];
    int j = d_idx[row];
    const float4* s1 = (const float4*)(x1 + (size_t)j * Dd);
    ((float4*)(out + (size_t)Nn * Dd + (size_t)row * Dd))[t] = s1[t];
}

// ---------------- launch ----------------
extern "C" void kernel_launch(void* const* d_in, const int* in_sizes, int n_in,
                              void* d_out, int out_size) {
    const float* x0 = (const float*)d_in[0];
    const float* x1 = (const float*)d_in[1];
    float* out = (float*)d_out;

    init_kernel<<<8, 1024>>>();
    rowsq_kernel<<<2 * (Nn / 256), 256>>>(x0, x1);

    dim3 gg(Nn / 128, Nn / 128);
    gemm_kernel<<<gg, 256>>>(x0, x1);

    dim3 tg(Nn / 32, Nn / 32), tb(32, 8);
    transpose_kernel<<<tg, tb>>>();

    for (int it = 0; it < 100; it++) {
        lse_pass_kernel<0><<<Nn, 256>>>();
        lse_pass_kernel<1><<<Nn, 256>>>();
    }

    argmax_kernel<<<Nn / 8, 256>>>();
    output_kernel<<<Nn, 128>>>(x0, x1, out);
}

// round 15
// speedup vs baseline: 1.4944x; 1.1473x over previous
#include <cuda_runtime.h>
#include <cuda_fp16.h>
#include <math.h>

#define Nn 8192
#define Dd 512
#define SEGCAP 192   // per-1024-segment candidate cap (exact fallback if hit)

// ---------------- static device scratch (symbol-access only) ----------------
static __device__ float  d_K  [(size_t)Nn * Nn];   // log_K fp32 (exact grid)
static __device__ float  d_KT [(size_t)Nn * Nn];   // transpose (same bits)
static __device__ __half d_Kh [(size_t)Nn * Nn];   // fp16 screening copy
static __device__ __half d_KTh[(size_t)Nn * Nn];   // fp16 screening copy (T)
static __device__ float d_alpha[Nn];
static __device__ float d_beta [Nn];
static __device__ float d_xsq[Nn];
static __device__ float d_ysq[Nn];
static __device__ int   d_idx[Nn];

// ---- FROZEN NUMERICS (Round 8 pass): XLA-CPU cephes exp, FMA-contracted ----
static __device__ __forceinline__ float exp_fma(float x) {
    x = fminf(x, 88.3762626647950f);
    x = fmaxf(x, -88.3762626647949f);
    float fx = floorf(__fmaf_rn(x, 1.44269504088896341f, 0.5f));
    float r  = __fmaf_rn(fx, -0.693359375f, x);
    r        = __fmaf_rn(fx,  2.12194440e-4f, r);
    float z  = __fmul_rn(r, r);
    float y  = __fmaf_rn(1.9875691500e-4f, r, 1.3981999507e-3f);
    y = __fmaf_rn(y, r, 8.3334519073e-3f);
    y = __fmaf_rn(y, r, 4.1665795894e-2f);
    y = __fmaf_rn(y, r, 1.6666665459e-1f);
    y = __fmaf_rn(y, r, 5.0000001201e-1f);
    y = __fmaf_rn(y, z, r);
    y = __fadd_rn(1.0f, y);
    int n = (int)fx;
    float s = __int_as_float((unsigned)(n + 127) << 23);
    return __fmul_rn(y, s);
}

// ---- FROZEN: XLA-CPU cephes log, FMA-contracted (S >= 1 here) ----
static __device__ __forceinline__ float log_fma(float x) {
    int bits = __float_as_int(x);
    int e = (bits >> 23) - 126;
    float mant = __int_as_float((bits & 0x007fffff) | 0x3f000000);  // [0.5,1)
    if (mant < 0.707106781186547524f) {
        e -= 1;
        mant = __fadd_rn(__fadd_rn(mant, mant), -1.0f);
    } else {
        mant = __fadd_rn(mant, -1.0f);
    }
    float z = __fmul_rn(mant, mant);
    float y = 7.0376836292e-2f;
    y = __fmaf_rn(y, mant, -1.1514610310e-1f);
    y = __fmaf_rn(y, mant,  1.1676998740e-1f);
    y = __fmaf_rn(y, mant, -1.2420140846e-1f);
    y = __fmaf_rn(y, mant,  1.4249322787e-1f);
    y = __fmaf_rn(y, mant, -1.6668057665e-1f);
    y = __fmaf_rn(y, mant,  2.0000714765e-1f);
    y = __fmaf_rn(y, mant, -2.4999993993e-1f);
    y = __fmaf_rn(y, mant,  3.3333331174e-1f);
    y = __fmul_rn(__fmul_rn(y, mant), z);
    float fe = (float)e;
    y = __fmaf_rn(fe, -2.12194440e-4f, y);
    y = __fmaf_rn(-0.5f, z, y);
    float res = __fadd_rn(mant, y);
    res = __fmaf_rn(fe, 0.693359375f, res);
    return res;
}

// ---------------- init ----------------
__global__ void init_kernel() {
    int i = blockIdx.x * blockDim.x + threadIdx.x;
    if (i < Nn) { d_beta[i] = 0.0f; d_alpha[i] = 0.0f; }
}

// ---------------- row squared norms: 8-slot FMA chains (FROZEN) -------------
__global__ void rowsq_kernel(const float* __restrict__ X0,
                             const float* __restrict__ X1) {
    int half = (gridDim.x * blockDim.x) >> 1;
    int g = blockIdx.x * blockDim.x + threadIdx.x;
    bool second = g >= half;
    int row = second ? (g - half) : g;
    const float* x = (second ? X1 : X0) + (size_t)row * Dd;
    float s[8];
#pragma unroll
    for (int i = 0; i < 8; i++) s[i] = 0.0f;
    for (int k = 0; k < Dd; k += 8) {
#pragma unroll
        for (int i = 0; i < 8; i++) {
            float v = x[k + i];
            s[i] = __fmaf_rn(v, v, s[i]);
        }
    }
    float w0 = __fadd_rn(s[0], s[4]);
    float w1 = __fadd_rn(s[1], s[5]);
    float w2 = __fadd_rn(s[2], s[6]);
    float w3 = __fadd_rn(s[3], s[7]);
    float r = __fadd_rn(__fadd_rn(w0, w2), __fadd_rn(w1, w3));
    if (second) d_ysq[row] = r; else d_xsq[row] = r;
}

// ------- GEMM -> K fp32 + fp16 copy. Double-buffered smem, K-tile 16. -------
// FROZEN numerics: each acc[i][j] is ONE ascending-k FMA chain.
__global__ void __launch_bounds__(256) gemm_kernel(const float* __restrict__ A,
                                                   const float* __restrict__ B) {
    __shared__ float As[2][16][128];
    __shared__ float Bs[2][16][128];
    int bi = blockIdx.y << 7, bj = blockIdx.x << 7;
    int t  = threadIdx.x;
    int tx = t & 15, ty = t >> 4;
    int lrow = t & 127;
    int kh   = (t >> 7) << 3;   // 0 or 8

    float acc[8][8];
#pragma unroll
    for (int i = 0; i < 8; i++)
#pragma unroll
        for (int j = 0; j < 8; j++) acc[i][j] = 0.f;

    const float* Ag = A + (size_t)(bi + lrow) * Dd + kh;
    const float* Bg = B + (size_t)(bj + lrow) * Dd + kh;

    float4 pa0 = *(const float4*)(Ag);
    float4 pa1 = *(const float4*)(Ag + 4);
    float4 pb0 = *(const float4*)(Bg);
    float4 pb1 = *(const float4*)(Bg + 4);

    As[0][kh + 0][lrow] = pa0.x; As[0][kh + 1][lrow] = pa0.y;
    As[0][kh + 2][lrow] = pa0.z; As[0][kh + 3][lrow] = pa0.w;
    As[0][kh + 4][lrow] = pa1.x; As[0][kh + 5][lrow] = pa1.y;
    As[0][kh + 6][lrow] = pa1.z; As[0][kh + 7][lrow] = pa1.w;
    Bs[0][kh + 0][lrow] = pb0.x; Bs[0][kh + 1][lrow] = pb0.y;
    Bs[0][kh + 2][lrow] = pb0.z; Bs[0][kh + 3][lrow] = pb0.w;
    Bs[0][kh + 4][lrow] = pb1.x; Bs[0][kh + 5][lrow] = pb1.y;
    Bs[0][kh + 6][lrow] = pb1.z; Bs[0][kh + 7][lrow] = pb1.w;
    __syncthreads();

    int buf = 0;
    for (int kt = 0; kt < Dd; kt += 16) {
        bool last = (kt + 16 >= Dd);
        if (!last) {
            pa0 = *(const float4*)(Ag + kt + 16);
            pa1 = *(const float4*)(Ag + kt + 20);
            pb0 = *(const float4*)(Bg + kt + 16);
            pb1 = *(const float4*)(Bg + kt + 20);
        }
#pragma unroll
        for (int k = 0; k < 16; k++) {          // ascending k — FROZEN chain
            float a[8], b[8];
            *(float4*)&a[0] = *(const float4*)&As[buf][k][(ty << 3)];
            *(float4*)&a[4] = *(const float4*)&As[buf][k][(ty << 3) + 4];
            *(float4*)&b[0] = *(const float4*)&Bs[buf][k][(tx << 3)];
            *(float4*)&b[4] = *(const float4*)&Bs[buf][k][(tx << 3) + 4];
#pragma unroll
            for (int i = 0; i < 8; i++)
#pragma unroll
                for (int j = 0; j < 8; j++)
                    acc[i][j] = __fmaf_rn(a[i], b[j], acc[i][j]);
        }
        if (!last) {
            int nb = buf ^ 1;
            As[nb][kh + 0][lrow] = pa0.x; As[nb][kh + 1][lrow] = pa0.y;
            As[nb][kh + 2][lrow] = pa0.z; As[nb][kh + 3][lrow] = pa0.w;
            As[nb][kh + 4][lrow] = pa1.x; As[nb][kh + 5][lrow] = pa1.y;
            As[nb][kh + 6][lrow] = pa1.z; As[nb][kh + 7][lrow] = pa1.w;
            Bs[nb][kh + 0][lrow] = pb0.x; Bs[nb][kh + 1][lrow] = pb0.y;
            Bs[nb][kh + 2][lrow] = pb0.z; Bs[nb][kh + 3][lrow] = pb0.w;
            Bs[nb][kh + 4][lrow] = pb1.x; Bs[nb][kh + 5][lrow] = pb1.y;
            Bs[nb][kh + 6][lrow] = pb1.z; Bs[nb][kh + 7][lrow] = pb1.w;
        }
        __syncthreads();
        buf ^= 1;
    }

    int row0 = bi + (ty << 3);
    int col0 = bj + (tx << 3);
    float xs[8], ys[8];
#pragma unroll
    for (int i = 0; i < 8; i++) xs[i] = d_xsq[row0 + i];
#pragma unroll
    for (int j = 0; j < 8; j++) ys[j] = d_ysq[col0 + j];
#pragma unroll
    for (int i = 0; i < 8; i++) {
        float o[8];
        __half hh[8];
#pragma unroll
        for (int j = 0; j < 8; j++) {
            float nrm  = __fadd_rn(xs[i], ys[j]);
            float cost = __fmaf_rn(-2.0f, acc[i][j], nrm);
            o[j] = __fdiv_rn(-cost, 0.1f);
            hh[j] = __float2half(o[j]);
        }
        *(float4*)&d_K[(size_t)(row0 + i) * Nn + col0]     = *(float4*)&o[0];
        *(float4*)&d_K[(size_t)(row0 + i) * Nn + col0 + 4] = *(float4*)&o[4];
        *(uint4*)&d_Kh[(size_t)(row0 + i) * Nn + col0]     = *(uint4*)hh;
    }
}

// ---------------- transpose: K -> KT (fp32) + KTh (fp16), one-time ----------
__global__ void transpose_kernel() {
    __shared__ float tile[32][33];
    int tx = threadIdx.x, ty = threadIdx.y;
    int xi = (blockIdx.x << 5) + tx;
    int yi = (blockIdx.y << 5) + ty;
#pragma unroll
    for (int j = 0; j < 32; j += 8)
        tile[ty + j][tx] = d_K[(size_t)(yi + j) * Nn + xi];
    __syncthreads();
    int xo = (blockIdx.y << 5) + tx;
    int yo = (blockIdx.x << 5) + ty;
#pragma unroll
    for (int j = 0; j < 32; j += 8) {
        float v = tile[tx][ty + j];
        d_KT [(size_t)(yo + j) * Nn + xo] = v;
        d_KTh[(size_t)(yo + j) * Nn + xo] = __float2half(v);
    }
}

// ====== LSE PASS: register-direct fp16 screen (no smem stage) ===============
// Sweep 1: stream z=fl(h2f(Kh)+v), track max only. Sweep 2 (L1-hot): rebuild
// z per 8 ascending elems/lane, 8-bit mask vs thr_s=m_s-96 (|z_scr-z|<=8,
// |m_s-m|<=8 => provable superset of {z>=m-70}, contains argmax), emit
// ascending via uniform ballot walk. Then exact fp32 gather, exact max,
// parallel exp, thread-0 FROZEN-order additions (8-slot alpha / seq beta).
template <int DIR>
__global__ void __launch_bounds__(256) lse_pass_kernel() {
    __shared__ float wmax[8];
    __shared__ float bmax_s, m_sh;
    __shared__ int   ok_s;
    __shared__ int   seg_cnt[8];
    __shared__ short seg_list[8][SEGCAP];
    __shared__ float seg_val[8][SEGCAP];

    int row = blockIdx.x;
    int t   = threadIdx.x;
    int lane = t & 31, wid = t >> 5;
    const __half* __restrict__ Hs = ((DIR == 0) ? d_Kh : d_KTh) + (size_t)row * Nn;
    const float*  __restrict__ Mx = ((DIR == 0) ? d_K  : d_KT ) + (size_t)row * Nn;
    const float*  __restrict__ vin = (DIR == 0) ? d_beta : d_alpha;

    int segbase = wid << 10;             // 1024 elems per warp segment

    // sweep 1: max only
    float lm = __int_as_float(0xff800000);
#pragma unroll
    for (int r2 = 0; r2 < 4; r2++) {
        int i0 = segbase + (r2 << 8) + (lane << 3);
        uint4 hv = *(const uint4*)(Hs + i0);
        __half2* hp = (__half2*)&hv;
        float4 b0 = *(const float4*)(vin + i0);
        float4 b1 = *(const float4*)(vin + i0 + 4);
        float2 f0 = __half22float2(hp[0]);
        float2 f1 = __half22float2(hp[1]);
        float2 f2 = __half22float2(hp[2]);
        float2 f3 = __half22float2(hp[3]);
        float z0 = __fadd_rn(f0.x, b0.x), z1 = __fadd_rn(f0.y, b0.y);
        float z2 = __fadd_rn(f1.x, b0.z), z3 = __fadd_rn(f1.y, b0.w);
        float z4 = __fadd_rn(f2.x, b1.x), z5 = __fadd_rn(f2.y, b1.y);
        float z6 = __fadd_rn(f3.x, b1.z), z7 = __fadd_rn(f3.y, b1.w);
        lm = fmaxf(lm, fmaxf(fmaxf(z0, z1), fmaxf(z2, z3)));
        lm = fmaxf(lm, fmaxf(fmaxf(z4, z5), fmaxf(z6, z7)));
    }
#pragma unroll
    for (int off = 16; off; off >>= 1)
        lm = fmaxf(lm, __shfl_down_sync(0xffffffffu, lm, off));
    if (lane == 0) { wmax[wid] = lm; seg_cnt[wid] = 0; }
    __syncthreads();

    if (wid == 0) {
        float m = (lane < 8) ? wmax[lane] : __int_as_float(0xff800000);
#pragma unroll
        for (int off = 4; off; off >>= 1)
            m = fmaxf(m, __shfl_down_sync(0xffffffffu, m, off));
        if (lane == 0) bmax_s = m;
    }
    __syncthreads();
    float thr_s = bmax_s - 96.0f;

    // sweep 2 (L1-hot): mask + ascending emission
    {
        int cnt = 0;
#pragma unroll
        for (int r2 = 0; r2 < 4; r2++) {
            int i0 = segbase + (r2 << 8) + (lane << 3);
            uint4 hv = *(const uint4*)(Hs + i0);
            __half2* hp = (__half2*)&hv;
            float4 b0 = *(const float4*)(vin + i0);
            float4 b1 = *(const float4*)(vin + i0 + 4);
            float2 f0 = __half22float2(hp[0]);
            float2 f1 = __half22float2(hp[1]);
            float2 f2 = __half22float2(hp[2]);
            float2 f3 = __half22float2(hp[3]);
            unsigned m8 = 0;
            m8 |= (__fadd_rn(f0.x, b0.x) >= thr_s) ? 1u   : 0u;
            m8 |= (__fadd_rn(f0.y, b0.y) >= thr_s) ? 2u   : 0u;
            m8 |= (__fadd_rn(f1.x, b0.z) >= thr_s) ? 4u   : 0u;
            m8 |= (__fadd_rn(f1.y, b0.w) >= thr_s) ? 8u   : 0u;
            m8 |= (__fadd_rn(f2.x, b1.x) >= thr_s) ? 16u  : 0u;
            m8 |= (__fadd_rn(f2.y, b1.y) >= thr_s) ? 32u  : 0u;
            m8 |= (__fadd_rn(f3.x, b1.z) >= thr_s) ? 64u  : 0u;
            m8 |= (__fadd_rn(f3.y, b1.w) >= thr_s) ? 128u : 0u;
            unsigned act = __ballot_sync(0xffffffffu, m8 != 0);
            while (act) {                      // act uniform across warp
                int la = __ffs(act) - 1;
                unsigned mm = __shfl_sync(0xffffffffu, m8, la);
                if (lane == 0) {
                    int base = (r2 << 8) + (la << 3);
                    while (mm) {
                        int b = __ffs(mm) - 1;
                        if (cnt < SEGCAP) seg_list[wid][cnt] = (short)(base + b);
                        cnt++;
                        mm &= mm - 1;
                    }
                }
                act &= act - 1;
            }
        }
        if (lane == 0) seg_cnt[wid] = cnt;
        __syncwarp();
        int cc = seg_cnt[wid]; if (cc > SEGCAP) cc = SEGCAP;
        // warp-parallel gather of EXACT fp32 z
        for (int p = lane; p < cc; p += 32) {
            int idx = segbase + seg_list[wid][p];
            seg_val[wid][p] = __fadd_rn(Mx[idx], vin[idx]);
        }
    }
    __syncthreads();

    if (t == 0) {
        bool ok = true;
#pragma unroll
        for (int w = 0; w < 8; w++) ok &= (seg_cnt[w] <= SEGCAP);
        ok_s = ok;
        if (ok) {
            float m = __int_as_float(0xff800000);
            for (int w = 0; w < 8; w++) {
                int cnt = seg_cnt[w];
                for (int p = 0; p < cnt; p++) m = fmaxf(m, seg_val[w][p]);
            }
            m_sh = m;
        }
    }
    __syncthreads();

    if (ok_s) {
        float m = m_sh;
        float thr = m - 70.0f;
        int cc = seg_cnt[wid];
        for (int p = lane; p < cc; p += 32) {
            float zv = seg_val[wid][p];
            seg_val[wid][p] = (zv >= thr) ? exp_fma(__fadd_rn(zv, -m)) : -1.0f;
        }
        __syncthreads();

        if (t == 0) {
            float S;
            if (DIR == 0) {
                float s[8];
#pragma unroll
                for (int i = 0; i < 8; i++) s[i] = 0.0f;
                for (int w = 0; w < 8; w++) {
                    int base = w << 10, cnt = seg_cnt[w];
                    for (int p = 0; p < cnt; p++) {
                        float e = seg_val[w][p];
                        if (e >= 0.0f) {
                            int idx = base + seg_list[w][p];
                            s[idx & 7] = __fadd_rn(s[idx & 7], e);
                        }
                    }
                }
                float w0 = __fadd_rn(s[0], s[4]);
                float w1 = __fadd_rn(s[1], s[5]);
                float w2 = __fadd_rn(s[2], s[6]);
                float w3 = __fadd_rn(s[3], s[7]);
                S = __fadd_rn(__fadd_rn(w0, w2), __fadd_rn(w1, w3));
            } else {
                float acc = 0.0f;
                for (int w = 0; w < 8; w++) {
                    int cnt = seg_cnt[w];
                    for (int p = 0; p < cnt; p++) {
                        float e = seg_val[w][p];
                        if (e >= 0.0f) acc = __fadd_rn(acc, e);
                    }
                }
                S = acc;
            }
            float res = -__fadd_rn(log_fma(S), m);
            if (DIR == 0) d_alpha[row] = res; else d_beta[row] = res;
        }
    } else if (t == 0) {
        // exact in-order fallback over full fp32 row (never expected)
        float m = __int_as_float(0xff800000);
        for (int q = 0; q < Nn; q++)
            m = fmaxf(m, __fadd_rn(Mx[q], vin[q]));
        float thr = m - 70.0f;
        float S;
        if (DIR == 0) {
            float s[8];
#pragma unroll
            for (int i = 0; i < 8; i++) s[i] = 0.0f;
            for (int q = 0; q < Nn; q++) {
                float zv = __fadd_rn(Mx[q], vin[q]);
                if (zv >= thr)
                    s[q & 7] = __fadd_rn(s[q & 7], exp_fma(__fadd_rn(zv, -m)));
            }
            float w0 = __fadd_rn(s[0], s[4]);
            float w1 = __fadd_rn(s[1], s[5]);
            float w2 = __fadd_rn(s[2], s[6]);
            float w3 = __fadd_rn(s[3], s[7]);
            S = __fadd_rn(__fadd_rn(w0, w2), __fadd_rn(w1, w3));
        } else {
            float acc = 0.0f;
            for (int q = 0; q < Nn; q++) {
                float zv = __fadd_rn(Mx[q], vin[q]);
                if (zv >= thr)
                    acc = __fadd_rn(acc, exp_fma(__fadd_rn(zv, -m)));
            }
            S = acc;
        }
        float res = -__fadd_rn(log_fma(S), m);
        if (DIR == 0) d_alpha[row] = res; else d_beta[row] = res;
    }
}

// ---------------- argmax over P = exp_fma(fl(fl(K+alpha)+beta)) (FROZEN) ----
__global__ void __launch_bounds__(256) argmax_kernel() {
    int rowbase = blockIdx.x << 3;
    int t = threadIdx.x;
    float a[8];
#pragma unroll
    for (int r = 0; r < 8; r++) a[r] = d_alpha[rowbase + r];

    float bv[8]; int bi_[8];
#pragma unroll
    for (int r = 0; r < 8; r++) { bv[r] = -1.0f; bi_[r] = Nn; }

    for (int c = t << 2; c < Nn; c += 1024) {
        float4 betav = *(const float4*)(d_beta + c);
#pragma unroll
        for (int r = 0; r < 8; r++) {
            float4 v = *(const float4*)(d_K + (size_t)(rowbase + r) * Nn + c);
            float w;
            w = exp_fma(__fadd_rn(__fadd_rn(v.x, a[r]), betav.x)); if (w > bv[r]) { bv[r] = w; bi_[r] = c; }
            w = exp_fma(__fadd_rn(__fadd_rn(v.y, a[r]), betav.y)); if (w > bv[r]) { bv[r] = w; bi_[r] = c + 1; }
            w = exp_fma(__fadd_rn(__fadd_rn(v.z, a[r]), betav.z)); if (w > bv[r]) { bv[r] = w; bi_[r] = c + 2; }
            w = exp_fma(__fadd_rn(__fadd_rn(v.w, a[r]), betav.w)); if (w > bv[r]) { bv[r] = w; bi_[r] = c + 3; }
        }
    }
#pragma unroll
    for (int r = 0; r < 8; r++) {
#pragma unroll
        for (int off = 16; off; off >>= 1) {
            float ov = __shfl_down_sync(0xffffffffu, bv[r], off);
            int   oi = __shfl_down_sync(0xffffffffu, bi_[r], off);
            if (ov > bv[r] || (ov == bv[r] && oi < bi_[r])) { bv[r] = ov; bi_[r] = oi; }
        }
    }
    __shared__ float svv[8][8];
    __shared__ int   sii[8][8];
    int wid = t >> 5, lane = t & 31;
    if (lane == 0) {
#pragma unroll
        for (int r = 0; r < 8; r++) { svv[r][wid] = bv[r]; sii[r][wid] = bi_[r]; }
    }
    __syncthreads();
    if (t < 8) {
        float V = -1.0f; int I = Nn;
#pragma unroll
        for (int w = 0; w < 8; w++) {
            float ov = svv[t][w]; int oi = sii[t][w];
            if (ov > V || (ov == V && oi < I)) { V = ov; I = oi; }
        }
        d_idx[rowbase + t] = I;
    }
}

// ---------------- out = concat(x0, x1[idx]) ----------------
__global__ void output_kernel(const float* __restrict__ x0,
                              const float* __restrict__ x1,
                              float* __restrict__ out) {
    int row = blockIdx.x;
    int t   = threadIdx.x;
    const float4* s0 = (const float4*)(x0 + (size_t)row * Dd);
    ((float4*)(out + (size_t)row * Dd))[t] = s0[t];
    int j = d_idx[row];
    const float4* s1 = (const float4*)(x1 + (size_t)j * Dd);
    ((float4*)(out + (size_t)Nn * Dd + (size_t)row * Dd))[t] = s1[t];
}

// ---------------- launch ----------------
extern "C" void kernel_launch(void* const* d_in, const int* in_sizes, int n_in,
                              void* d_out, int out_size) {
    const float* x0 = (const float*)d_in[0];
    const float* x1 = (const float*)d_in[1];
    float* out = (float*)d_out;

    init_kernel<<<8, 1024>>>();
    rowsq_kernel<<<2 * (Nn / 256), 256>>>(x0, x1);

    dim3 gg(Nn / 128, Nn / 128);
    gemm_kernel<<<gg, 256>>>(x0, x1);

    dim3 tg(Nn / 32, Nn / 32), tb(32, 8);
    transpose_kernel<<<tg, tb>>>();

    for (int it = 0; it < 100; it++) {
        lse_pass_kernel<0><<<Nn, 256>>>();
        lse_pass_kernel<1><<<Nn, 256>>>();
    }

    argmax_kernel<<<Nn / 8, 256>>>();
    output_kernel<<<Nn, 128>>>(x0, x1, out);
}